// round 15
// baseline (speedup 1.0000x reference)
#include <cuda_runtime.h>
#include <cstdint>

// Problem constants
#define B_ROWS   65536
#define N_SPARSE 26
#define VOCAB    5000
#define N_DENSE  13

#define THREADS    1024
#define ROWS_PB    448        // 2 subs/row -> 896 worker threads
#define NBLOCKS    147        // 146*448=65408, last block 128 rows
#define CHUNK_ROWS 112
#define N_CHUNKS   4

#define N_CACHED 18           // features [0,18) via smem; [18,26) + crosses direct
#define PASS_NF  2
#define N_PASSES 9
#define NBUF     4            // 4-deep slice ring: no dependent issue chain

// Dynamic smem layout (bytes), 16B-aligned
#define BUF_BYTES   (PASS_NF * VOCAB * 4)       // 40000
#define IDX_OFF     (NBUF * BUF_BYTES)          // 160000
#define IDX_BYTES   (ROWS_PB * N_SPARSE * 4)    // 46592
#define MBAR_OFF    (IDX_OFF + IDX_BYTES)       // 206592
#define SMEM_TOTAL  (MBAR_OFF + 8 * 8)          // 206656 (< 227KB max dyn smem)

__device__ __forceinline__ uint32_t smem_u32(const void* p) {
    return (uint32_t)__cvta_generic_to_shared(p);
}
__device__ __forceinline__ void mbar_init(uint32_t mbar, uint32_t count) {
    asm volatile("mbarrier.init.shared.b64 [%0], %1;" :: "r"(mbar), "r"(count) : "memory");
}
__device__ __forceinline__ void mbar_expect_tx(uint32_t mbar, uint32_t bytes) {
    asm volatile("mbarrier.arrive.expect_tx.shared.b64 _, [%0], %1;"
                 :: "r"(mbar), "r"(bytes) : "memory");
}
__device__ __forceinline__ void mbar_wait(uint32_t mbar, uint32_t parity) {
    uint32_t done = 0;
    while (!done) {
        asm volatile(
            "{\n\t.reg .pred p;\n\t"
            "mbarrier.try_wait.parity.acquire.cta.shared::cta.b64 p, [%1], %2, 0x989680;\n\t"
            "selp.b32 %0, 1, 0, p;\n\t}"
            : "=r"(done) : "r"(mbar), "r"(parity) : "memory");
    }
}
__device__ __forceinline__ void bulk_g2s(uint32_t dst, const void* src,
                                         uint32_t bytes, uint32_t mbar) {
    asm volatile(
        "cp.async.bulk.shared::cta.global.mbarrier::complete_tx::bytes [%0], [%1], %2, [%3];"
        :: "r"(dst), "l"(src), "r"(bytes), "r"(mbar) : "memory");
}

__global__ __launch_bounds__(THREADS, 1) void wide_kernel(
    const float* __restrict__ dense,        // [B, 13]
    const float* __restrict__ emb_table,    // [26, 5000]
    const float* __restrict__ cross_table0, // [25e6]
    const float* __restrict__ cross_table1, // [25e6]
    const float* __restrict__ dense_w,      // [13]
    const int*   __restrict__ sparse_idx,   // [B, 26] int32
    float*       __restrict__ out)          // [B]
{
    extern __shared__ __align__(16) char smem[];
    int* s_idx = (int*)(smem + IDX_OFF);

    const uint32_t mb_io0 = smem_u32(smem + MBAR_OFF);        // 4 io chunk barriers
    const uint32_t mb_b0  = smem_u32(smem + MBAR_OFF + 32);   // 4 slice barriers
    const uint32_t buf0_s = smem_u32(smem);

    const int tid  = threadIdx.x;
    const int row0 = blockIdx.x * ROWS_PB;
    const int rows = min(ROWS_PB, B_ROWS - row0);

    if (tid == 0) {
        #pragma unroll
        for (int c = 0; c < N_CHUNKS; c++) mbar_init(mb_io0 + 8 * c, 1);
        #pragma unroll
        for (int s = 0; s < NBUF; s++)     mbar_init(mb_b0 + 8 * s, 1);
    }
    __syncthreads();

    // Issue all initial async copies: 4 idx chunks + 4 table slices (full ring).
    if (tid == 0) {
        #pragma unroll
        for (int c = 0; c < N_CHUNKS; c++) {
            const int crow0 = c * CHUNK_ROWS;
            const int crows = max(0, min(CHUNK_ROWS, rows - crow0));
            const uint32_t ib = (uint32_t)crows * N_SPARSE * 4;
            mbar_expect_tx(mb_io0 + 8 * c, ib);   // 0 bytes -> flips immediately
            if (crows > 0) {
                bulk_g2s(smem_u32(s_idx + crow0 * N_SPARSE),
                         sparse_idx + (size_t)(row0 + crow0) * N_SPARSE, ib, mb_io0 + 8 * c);
            }
        }
        #pragma unroll
        for (int s = 0; s < NBUF; s++) {
            mbar_expect_tx(mb_b0 + 8 * s, BUF_BYTES);
            bulk_g2s(buf0_s + s * BUF_BYTES, emb_table + s * PASS_NF * VOCAB,
                     BUF_BYTES, mb_b0 + 8 * s);
        }
    }

    const int  sub    = tid & 1;             // 2 sub-threads per row
    const int  rawrow = tid >> 1;
    const bool active = (rawrow < rows);

    // Wait only for this thread's own idx chunk.
    const int chunk = min(rawrow / CHUNK_ROWS, N_CHUNKS - 1);
    mbar_wait(mb_io0 + 8 * chunk, 0);

    const int* my = &s_idx[rawrow * N_SPARSE];
    float acc = 0.0f;

    if (active) {
        // Direct gathers: 1 cross (DRAM) + 4 emb features per sub.
        if (sub == 0) {
            acc += __ldg(&cross_table0[my[0] * VOCAB + my[1]]);     // DRAM first
            #pragma unroll
            for (int f = N_CACHED; f < 22; f++)                     // 18..21
                acc += __ldg(&emb_table[f * VOCAB + my[f]]);
        } else {
            acc += __ldg(&cross_table1[my[2] * VOCAB + my[3]]);
            #pragma unroll
            for (int f = 22; f < N_SPARSE; f++)                     // 22..25
                acc += __ldg(&emb_table[f * VOCAB + my[f]]);
        }

        // Dense dot straight from gmem (contiguous 28B/24B per sub, coalesced
        // across adjacent-row threads), pair-split (7 / 6).
        const float* dr = &dense[(size_t)(row0 + rawrow) * N_DENSE];
        if (sub == 0) {
            #pragma unroll
            for (int d = 0; d < 7; d++) acc += __ldg(&dr[d]) * __ldg(&dense_w[d]);
        } else {
            #pragma unroll
            for (int d = 7; d < N_DENSE; d++) acc += __ldg(&dr[d]) * __ldg(&dense_w[d]);
        }
    }

    // 4-deep ring of cached passes: 9 passes x 2 features over [0, 18).
    // Slice p+4 is issued after pass p -> 3 passes of slack, chain never binds.
    #pragma unroll
    for (int p = 0; p < N_PASSES; p++) {
        const int b = p & 3;
        mbar_wait(mb_b0 + 8 * b, (p >> 2) & 1);

        if (active) {
            const float* tb = (const float*)(smem + b * BUF_BYTES);
            const int f0 = p * PASS_NF;
            acc += tb[sub * VOCAB + my[f0 + sub]];   // 1 feature per sub
        }

        __syncthreads();   // all consumers done with buffer b

        if (p + NBUF < N_PASSES && tid == 0) {
            mbar_expect_tx(mb_b0 + 8 * b, BUF_BYTES);
            bulk_g2s(buf0_s + b * BUF_BYTES,
                     emb_table + (p + NBUF) * PASS_NF * VOCAB,
                     BUF_BYTES, mb_b0 + 8 * b);
        }
    }

    // Pair combine + store
    acc += __shfl_xor_sync(0xFFFFFFFFu, acc, 1);
    if (active && sub == 0) out[row0 + rawrow] = acc;
}

extern "C" void kernel_launch(void* const* d_in, const int* in_sizes, int n_in,
                              void* d_out, int out_size)
{
    const float* dense        = nullptr;
    const float* emb_table    = nullptr;
    const float* cross_table0 = nullptr;
    const float* cross_table1 = nullptr;
    const float* dense_w      = nullptr;
    const int*   sparse_idx   = nullptr;

    for (int i = 0; i < n_in; i++) {
        const long long sz = in_sizes[i];
        if      (sz == (long long)B_ROWS * N_DENSE)   dense      = (const float*)d_in[i];
        else if (sz == (long long)N_SPARSE * VOCAB)   emb_table  = (const float*)d_in[i];
        else if (sz == (long long)VOCAB * VOCAB) {
            if (!cross_table0) cross_table0 = (const float*)d_in[i];
            else               cross_table1 = (const float*)d_in[i];
        }
        else if (sz == N_DENSE)                       dense_w    = (const float*)d_in[i];
        else if (sz == (long long)B_ROWS * N_SPARSE)  sparse_idx = (const int*)d_in[i];
    }

    float* out = (float*)d_out;

    static bool attr_set = false;
    if (!attr_set) {
        cudaFuncSetAttribute(wide_kernel,
                             cudaFuncAttributeMaxDynamicSharedMemorySize, SMEM_TOTAL);
        attr_set = true;
    }

    wide_kernel<<<NBLOCKS, THREADS, SMEM_TOTAL>>>(dense, emb_table,
                                                  cross_table0, cross_table1,
                                                  dense_w, sparse_idx, out);
}